// round 1
// baseline (speedup 1.0000x reference)
#include <cuda_runtime.h>
#include <cuda_bf16.h>
#include <math.h>

#define BSZ  4
#define TLEN 2048
#define DIN_ 512
#define DM_  1024
#define DO_  1024
#define LNUM 2
#define DS_  16
#define DC_  4
#define DI_  2048
#define DTR_ 64
#define MROWS (BSZ*TLEN)          // 8192
#define DBCW  (DTR_ + 2*DS_)      // 96

// ---------------- scratch (device globals; no allocation allowed) -----------
__device__ float g_x   [(size_t)MROWS*DM_];      // running activation / residual
__device__ float g_xn  [(size_t)MROWS*DM_];      // layernorm output
__device__ float g_xz  [(size_t)MROWS*2*DI_];    // in_proj output (xi | z)
__device__ float g_u   [(size_t)MROWS*DI_];      // conv+silu output
__device__ float g_dbc [(size_t)MROWS*DBCW];     // x_proj output (dt|B|C)
__device__ float g_delta[(size_t)MROWS*DI_];     // softplus(dt@dpw+b)
__device__ float g_y   [(size_t)MROWS*DI_];      // scan output -> gated
__device__ float g_ob  [(size_t)MROWS*DO_];      // pre-mean output
__device__ int   g_len [BSZ];

// ---------------- mask decoding (bool/int32/float32 robust) -----------------
__global__ void detect_mask_kernel(const unsigned char* __restrict__ mb) {
    __shared__ int s_weird, s_off, s_cnt[BSZ];
    int tid = threadIdx.x;
    if (tid == 0) { s_weird = 0; s_off = 0; }
    if (tid < BSZ) s_cnt[tid] = 0;
    __syncthreads();
    for (int i = tid; i < BSZ*TLEN; i += blockDim.x) {
        unsigned char c = mb[i];
        if (c > 1) s_weird = 1;
        else if (c && (i & 3)) s_off = 1;
    }
    __syncthreads();
    int mode = s_weird ? 2 : (s_off ? 0 : 1);   // 0=bool bytes, 1=int32, 2=float32
    for (int i = tid; i < BSZ*TLEN; i += blockDim.x) {
        int b = i / TLEN;
        int v;
        if (mode == 0)      v = mb[i];
        else if (mode == 1) v = ((const int*)mb)[i];
        else                v = (((const float*)mb)[i] != 0.0f);
        if (!v) atomicAdd(&s_cnt[b], 1);        // count of valid (non-masked) steps
    }
    __syncthreads();
    if (tid < BSZ) g_len[tid] = s_cnt[tid];
}

// ---------------- generic fp32 SGEMM:  C = A(MxK) * W(NxK)^T  ---------------
// flags: bit0 = accumulate into C, bit1 = softplus epilogue
__global__ __launch_bounds__(256, 2) void gemm_nt(
    const float* __restrict__ A, int lda,
    const float* __restrict__ W, int ldb,
    const float* __restrict__ bias,
    float* __restrict__ C, int ldc,
    int M, int N, int K, int flags)
{
    __shared__ float As[8][128];
    __shared__ float Bs[8][128];
    const int tid = threadIdx.x;
    const int bm = blockIdx.y * 128;
    const int bn = blockIdx.x * 128;
    const int lr = tid >> 1;
    const int lk = (tid & 1) << 2;
    const float* Ap = A + (size_t)(bm + lr) * lda + lk;
    const float* Bp = W + (size_t)(bn + lr) * ldb + lk;
    const bool bval = (bn + lr) < N;

    float acc[8][8];
#pragma unroll
    for (int i = 0; i < 8; i++)
#pragma unroll
        for (int j = 0; j < 8; j++) acc[i][j] = 0.f;

    const int tx = (tid & 15) << 3;
    const int ty = (tid >> 4) << 3;

    for (int k0 = 0; k0 < K; k0 += 8) {
        float4 a4 = *(const float4*)(Ap + k0);
        float4 b4 = make_float4(0.f, 0.f, 0.f, 0.f);
        if (bval) b4 = *(const float4*)(Bp + k0);
        As[lk+0][lr] = a4.x; As[lk+1][lr] = a4.y;
        As[lk+2][lr] = a4.z; As[lk+3][lr] = a4.w;
        Bs[lk+0][lr] = b4.x; Bs[lk+1][lr] = b4.y;
        Bs[lk+2][lr] = b4.z; Bs[lk+3][lr] = b4.w;
        __syncthreads();
#pragma unroll
        for (int kk = 0; kk < 8; kk++) {
            float ra[8], rb[8];
            *(float4*)(ra)     = *(const float4*)&As[kk][ty];
            *(float4*)(ra + 4) = *(const float4*)&As[kk][ty + 4];
            *(float4*)(rb)     = *(const float4*)&Bs[kk][tx];
            *(float4*)(rb + 4) = *(const float4*)&Bs[kk][tx + 4];
#pragma unroll
            for (int i = 0; i < 8; i++)
#pragma unroll
                for (int j = 0; j < 8; j++)
                    acc[i][j] += ra[i] * rb[j];
        }
        __syncthreads();
    }

#pragma unroll
    for (int i = 0; i < 8; i++) {
        int row = bm + ty + i;
        float* Crow = C + (size_t)row * ldc;
#pragma unroll
        for (int j = 0; j < 8; j++) {
            int col = bn + tx + j;
            if (col < N) {
                float v = acc[i][j];
                if (bias) v += bias[col];
                if (flags & 2) v = (v > 20.f) ? v : log1pf(expf(v));
                if (flags & 1) v += Crow[col];
                Crow[col] = v;
            }
        }
    }
}

// ---------------- layernorm over DM=1024, one block per row -----------------
__global__ void layernorm_kernel(const float* __restrict__ x,
                                 const float* __restrict__ w,
                                 const float* __restrict__ bb,
                                 float* __restrict__ y)
{
    int row = blockIdx.x, tid = threadIdx.x;
    const float* xr = x + (size_t)row * DM_;
    float4 v = *(const float4*)(xr + tid * 4);
    float s  = v.x + v.y + v.z + v.w;
    float ss = v.x*v.x + v.y*v.y + v.z*v.z + v.w*v.w;
#pragma unroll
    for (int o = 16; o > 0; o >>= 1) {
        s  += __shfl_xor_sync(0xffffffffu, s, o);
        ss += __shfl_xor_sync(0xffffffffu, ss, o);
    }
    __shared__ float rs_[8], rss[8];
    int wid = tid >> 5, lane = tid & 31;
    if (lane == 0) { rs_[wid] = s; rss[wid] = ss; }
    __syncthreads();
    if (tid == 0) {
        float ts = 0.f, tss = 0.f;
        for (int i = 0; i < 8; i++) { ts += rs_[i]; tss += rss[i]; }
        rs_[0] = ts; rss[0] = tss;
    }
    __syncthreads();
    float mu  = rs_[0] * (1.f / DM_);
    float var = rss[0] * (1.f / DM_) - mu * mu;
    float inv = rsqrtf(var + 1e-5f);
    float4 wv = *(const float4*)(w + tid * 4);
    float4 bv = *(const float4*)(bb + tid * 4);
    float4 o;
    o.x = (v.x - mu) * inv * wv.x + bv.x;
    o.y = (v.y - mu) * inv * wv.y + bv.y;
    o.z = (v.z - mu) * inv * wv.z + bv.z;
    o.w = (v.w - mu) * inv * wv.w + bv.w;
    *(float4*)(y + (size_t)row * DM_ + tid * 4) = o;
}

// ---------------- causal depthwise conv (DC=4) + bias + silu ----------------
__global__ void conv_silu_kernel(const float* __restrict__ cw,
                                 const float* __restrict__ cb)
{
    size_t idx = (size_t)blockIdx.x * blockDim.x + threadIdx.x;
    int d = (int)(idx % DI_);
    size_t r = idx / DI_;
    int t = (int)(r % TLEN);
    const size_t base = r * (size_t)(2 * DI_) + d;
    float acc = cb[d];
#pragma unroll
    for (int j = 0; j < DC_; j++) {
        int tt = t - (DC_ - 1) + j;
        if (tt >= 0)
            acc += g_xz[base + (size_t)(j - (DC_ - 1)) * (2 * DI_)] * cw[d * DC_ + j];
    }
    float sg = 1.f / (1.f + __expf(-acc));
    g_u[r * DI_ + d] = acc * sg;
}

// ---------------- selective scan: one warp = 2 channels x 16 states ---------
__global__ void scan_kernel(const float* __restrict__ Alog,
                            const float* __restrict__ Dp)
{
    int gw   = (int)((blockIdx.x * blockDim.x + threadIdx.x) >> 5);
    int lane = threadIdx.x & 31;
    int b  = gw >> 10;            // / (DI/2)
    int dp = gw & 1023;
    int s  = lane & 15;
    int half = lane >> 4;
    int d = dp * 2 + half;

    float Av = -expf(Alog[d * DS_ + s]);
    float Dv = Dp[d];
    float h = 0.f;

    for (int t = 0; t < TLEN; t++) {
        size_t row = (size_t)b * TLEN + t;
        float delta = g_delta[row * DI_ + d];
        float u     = g_u    [row * DI_ + d];
        float Bv = g_dbc[row * DBCW + DTR_ + s];
        float Cv = g_dbc[row * DBCW + DTR_ + DS_ + s];
        float e = __expf(delta * Av);
        h = h * e + (delta * u) * Bv;
        float p = h * Cv;
        p += __shfl_xor_sync(0xffffffffu, p, 1);
        p += __shfl_xor_sync(0xffffffffu, p, 2);
        p += __shfl_xor_sync(0xffffffffu, p, 4);
        p += __shfl_xor_sync(0xffffffffu, p, 8);
        if (s == 0) g_y[row * DI_ + d] = p + u * Dv;
    }
}

// ---------------- gate: y *= silu(z) ----------------------------------------
__global__ void gate_kernel()
{
    size_t idx = (size_t)blockIdx.x * blockDim.x + threadIdx.x;
    int d = (int)(idx % DI_);
    size_t r = idx / DI_;
    float z = g_xz[r * (size_t)(2 * DI_) + DI_ + d];
    float sg = z / (1.f + __expf(-z));
    g_y[idx] *= sg;
}

// ---------------- masked mean over time -------------------------------------
__global__ void mean_kernel(float* __restrict__ out)
{
    int b = blockIdx.y;
    int o = blockIdx.x * blockDim.x + threadIdx.x;
    int len = g_len[b];
    if (len < 1) len = 1;
    const float* p = g_ob + ((size_t)b * TLEN) * DO_ + o;
    float sum = 0.f;
    for (int t = 0; t < len; t++) sum += p[(size_t)t * DO_];
    out[b * DO_ + o] = sum / (float)len;
}

// ---------------- launch ----------------------------------------------------
extern "C" void kernel_launch(void* const* d_in, const int* in_sizes, int n_in,
                              void* d_out, int out_size)
{
    const float* features  = (const float*)d_in[0];
    const void*  mask      = d_in[1];
    const float* inp_w     = (const float*)d_in[2];
    const float* inp_b     = (const float*)d_in[3];
    const float* norm_w    = (const float*)d_in[4];
    const float* norm_b    = (const float*)d_in[5];
    const float* in_proj_w = (const float*)d_in[6];
    const float* conv_w    = (const float*)d_in[7];
    const float* conv_b    = (const float*)d_in[8];
    const float* x_proj_w  = (const float*)d_in[9];
    const float* dt_proj_w = (const float*)d_in[10];
    const float* dt_proj_b = (const float*)d_in[11];
    const float* A_log     = (const float*)d_in[12];
    const float* Dskip     = (const float*)d_in[13];
    const float* mout_w    = (const float*)d_in[14];
    const float* out_w     = (const float*)d_in[15];
    const float* out_b     = (const float*)d_in[16];
    float* out = (float*)d_out;

    float *px, *pxn, *pxz, *pu, *pdbc, *pdelta, *py, *pob;
    cudaGetSymbolAddress((void**)&px,     g_x);
    cudaGetSymbolAddress((void**)&pxn,    g_xn);
    cudaGetSymbolAddress((void**)&pxz,    g_xz);
    cudaGetSymbolAddress((void**)&pu,     g_u);
    cudaGetSymbolAddress((void**)&pdbc,   g_dbc);
    cudaGetSymbolAddress((void**)&pdelta, g_delta);
    cudaGetSymbolAddress((void**)&py,     g_y);
    cudaGetSymbolAddress((void**)&pob,    g_ob);

    detect_mask_kernel<<<1, 256>>>((const unsigned char*)mask);

    // x = features @ inp_w^T + inp_b
    gemm_nt<<<dim3(DM_/128, MROWS/128), 256>>>(
        features, DIN_, inp_w, DIN_, inp_b, px, DM_, MROWS, DM_, DIN_, 0);

    for (int l = 0; l < LNUM; l++) {
        layernorm_kernel<<<MROWS, 256>>>(px, norm_w + l*DM_, norm_b + l*DM_, pxn);

        // xz = xn @ in_proj_w^T
        gemm_nt<<<dim3(2*DI_/128, MROWS/128), 256>>>(
            pxn, DM_, in_proj_w + (size_t)l*2*DI_*DM_, DM_, nullptr,
            pxz, 2*DI_, MROWS, 2*DI_, DM_, 0);

        conv_silu_kernel<<<(MROWS*(size_t)DI_)/256, 256>>>(
            conv_w + (size_t)l*DI_*DC_, conv_b + l*DI_);

        // dbc = u @ x_proj_w^T   (N=96 guarded tile)
        gemm_nt<<<dim3(1, MROWS/128), 256>>>(
            pu, DI_, x_proj_w + (size_t)l*DBCW*DI_, DI_, nullptr,
            pdbc, DBCW, MROWS, DBCW, DI_, 0);

        // delta = softplus(dt @ dt_proj_w^T + dt_proj_b)
        gemm_nt<<<dim3(DI_/128, MROWS/128), 256>>>(
            pdbc, DBCW, dt_proj_w + (size_t)l*DI_*DTR_, DTR_,
            dt_proj_b + l*DI_, pdelta, DI_, MROWS, DI_, DTR_, 2);

        // selective scan  (4096 warps)
        scan_kernel<<<512, 256>>>(A_log + (size_t)l*DI_*DS_, Dskip + l*DI_);

        gate_kernel<<<(MROWS*(size_t)DI_)/256, 256>>>();

        // x += (y*silu(z)) @ mout_w^T   (residual via accumulate)
        gemm_nt<<<dim3(DM_/128, MROWS/128), 256>>>(
            py, DI_, mout_w + (size_t)l*DM_*DI_, DI_, nullptr,
            px, DM_, MROWS, DM_, DI_, 1);
    }

    // ob = x @ out_w^T + out_b
    gemm_nt<<<dim3(DO_/128, MROWS/128), 256>>>(
        px, DM_, out_w, DM_, out_b, pob, DO_, MROWS, DO_, DM_, 0);

    mean_kernel<<<dim3(DO_/256, BSZ), 256>>>(out);
}

// round 3
// speedup vs baseline: 1.7141x; 1.7141x over previous
#include <cuda_runtime.h>
#include <cuda_bf16.h>
#include <math.h>
#include <stdint.h>

#define BSZ  4
#define TLEN 2048
#define DIN_ 512
#define DM_  1024
#define DO_  1024
#define LNUM 2
#define DS_  16
#define DC_  4
#define DI_  2048
#define DTR_ 64
#define MROWS (BSZ*TLEN)          // 8192
#define DBCW  (DTR_ + 2*DS_)      // 96

// ---------------- scratch (device globals; no allocation allowed) -----------
__device__ float g_x   [(size_t)MROWS*DM_];
__device__ float g_xn  [(size_t)MROWS*DM_];
__device__ float g_xz  [(size_t)MROWS*2*DI_];
__device__ float g_u   [(size_t)MROWS*DI_];
__device__ float g_dbc [(size_t)MROWS*DBCW];
__device__ float g_delta[(size_t)MROWS*DI_];
__device__ float g_y   [(size_t)MROWS*DI_];
__device__ float g_ob  [(size_t)MROWS*DO_];
__device__ int   g_len [BSZ];
// split-precision bf16 operand buffers
__device__ __nv_bfloat16 g_abig[(size_t)MROWS*6144];   // M x 3K (max 3K=6144)
__device__ __nv_bfloat16 g_wbig[(size_t)4096*3072];    // N x 3K

// =================== PTX helpers (baseline compute_103 ISA) =================
__device__ __forceinline__ uint32_t smem_u32(const void* p) {
    uint32_t a;
    asm("{ .reg .u64 t; cvta.to.shared.u64 t, %1; cvt.u32.u64 %0, t; }" : "=r"(a) : "l"(p));
    return a;
}
__device__ __forceinline__ void cp_async16(uint32_t d, const void* g, int sz) {
    asm volatile("cp.async.cg.shared.global [%0], [%1], 16, %2;"
                 :: "r"(d), "l"(g), "r"(sz) : "memory");
}
__device__ __forceinline__ void ldm4(uint32_t* r, uint32_t addr) {
    asm volatile("ldmatrix.sync.aligned.m8n8.x4.shared.b16 {%0,%1,%2,%3}, [%4];"
        : "=r"(r[0]), "=r"(r[1]), "=r"(r[2]), "=r"(r[3]) : "r"(addr));
}
__device__ __forceinline__ void mma16816(float* d, const uint32_t* a,
                                         uint32_t b0, uint32_t b1) {
    asm volatile("mma.sync.aligned.m16n8k16.row.col.f32.bf16.bf16.f32 "
        "{%0,%1,%2,%3}, {%4,%5,%6,%7}, {%8,%9}, {%0,%1,%2,%3};"
        : "+f"(d[0]), "+f"(d[1]), "+f"(d[2]), "+f"(d[3])
        : "r"(a[0]), "r"(a[1]), "r"(a[2]), "r"(a[3]), "r"(b0), "r"(b1));
}

// ---------------- split conversion: v -> (hi, lo) bf16, K tripled -----------
// mode 0 (activations): [hi | hi | lo] ; mode 1 (weights): [hi | lo | hi]
__global__ void convert_split(const float* __restrict__ src, int lda,
                              __nv_bfloat16* __restrict__ dst,
                              int rows, int K, int mode)
{
    size_t idx = (size_t)blockIdx.x * blockDim.x + threadIdx.x;
    if (idx >= (size_t)rows * K) return;
    int row = (int)(idx / K);
    int c   = (int)(idx % K);
    float v = src[(size_t)row * lda + c];
    __nv_bfloat16 hi = __float2bfloat16(v);
    __nv_bfloat16 lo = __float2bfloat16(v - __bfloat162float(hi));
    size_t base = (size_t)row * (3 * (size_t)K);
    if (mode == 0) {
        dst[base + c] = hi; dst[base + K + c] = hi; dst[base + 2*K + c] = lo;
    } else {
        dst[base + c] = hi; dst[base + K + c] = lo; dst[base + 2*K + c] = hi;
    }
}

// ---------------- mma.sync bf16 GEMM: C = Abig(M x K3) * Wbig(N x K3)^T -----
// flags: bit0 = accumulate into C, bit1 = softplus epilogue
#define STAGES 3
#define STAGE_BYTES 32768          // A 16KB + B 16KB per stage (BK=64 bf16)
#define GTC_SMEM (STAGES * STAGE_BYTES)

__global__ __launch_bounds__(256)
void gemm_mma(const __nv_bfloat16* __restrict__ A, int lda3,
              const __nv_bfloat16* __restrict__ W, int ldb3,
              const float* __restrict__ bias,
              float* __restrict__ C, int ldc,
              int N, int K3, int flags)
{
    extern __shared__ char smem[];
    const uint32_t sbase = smem_u32(smem);
    const int tid  = threadIdx.x;
    const int lane = tid & 31, wid = tid >> 5;
    const int bm = blockIdx.y << 7, bn = blockIdx.x << 7;
    const int warpM = (wid & 1) << 6;    // 0 / 64
    const int warpN = (wid >> 1) << 5;   // 0 / 32 / 64 / 96

    const int nch = (K3 + 63) >> 6;

    float acc[4][4][4];
#pragma unroll
    for (int i = 0; i < 4; i++)
#pragma unroll
        for (int j = 0; j < 4; j++)
#pragma unroll
            for (int k = 0; k < 4; k++) acc[i][j][k] = 0.f;

    // ldmatrix per-thread row mapping
    const int r_a   = (lane & 7) + ((lane >> 3) & 1) * 8;  // 0..15
    const int cpart = lane >> 4;                            // 0/1
    const int rx    = lane & 7;                             // row & 7
    uint32_t a_row[4], b_row[2];
#pragma unroll
    for (int mi = 0; mi < 4; mi++) a_row[mi] = (uint32_t)(warpM + mi*16 + r_a) * 128u;
#pragma unroll
    for (int bi = 0; bi < 2; bi++) b_row[bi] = 16384u + (uint32_t)(warpN + bi*16 + r_a) * 128u;

    // loader: 4 16B chunks each for A and B per thread per stage
    auto load_stage = [&](int c, int stg) {
        uint32_t sA = sbase + (uint32_t)stg * STAGE_BYTES;
#pragma unroll
        for (int i = 0; i < 4; i++) {
            int cid = tid + (i << 8);
            int row = cid >> 3, ch = cid & 7;
            int kk  = (c << 6) + (ch << 3);        // bf16 index along K3
            uint32_t off = (uint32_t)row * 128u + (uint32_t)((ch ^ (row & 7)) << 4);
            int aok = (kk < K3) ? 16 : 0;
            cp_async16(sA + off, A + (size_t)(bm + row) * lda3 + kk, aok);
            int brow = bn + row;
            int bok = (kk < K3 && brow < N) ? 16 : 0;
            cp_async16(sA + 16384u + off,
                       W + (size_t)(bok ? brow : 0) * ldb3 + kk, bok);
        }
        asm volatile("cp.async.commit_group;" ::: "memory");
    };

    for (int s = 0; s < STAGES - 1 && s < nch; s++) load_stage(s, s);

    for (int c = 0; c < nch; c++) {
        asm volatile("cp.async.wait_group %0;" :: "n"(STAGES - 2) : "memory");
        __syncthreads();
        const uint32_t sA = sbase + (uint32_t)(c % STAGES) * STAGE_BYTES;
#pragma unroll
        for (int ks = 0; ks < 4; ks++) {
            const uint32_t csel = (uint32_t)(((2*ks + cpart) ^ rx) << 4);
            uint32_t af[4][4], bf[2][4];
#pragma unroll
            for (int mi = 0; mi < 4; mi++) ldm4(af[mi], sA + a_row[mi] + csel);
#pragma unroll
            for (int bi = 0; bi < 2; bi++) ldm4(bf[bi], sA + b_row[bi] + csel);
#pragma unroll
            for (int mi = 0; mi < 4; mi++) {
#pragma unroll
                for (int ni = 0; ni < 4; ni++) {
                    const int bi = ni >> 1, sel = ni & 1;
                    mma16816(acc[mi][ni], af[mi], bf[bi][sel], bf[bi][sel + 2]);
                }
            }
        }
        if (c + STAGES - 1 < nch) load_stage(c + STAGES - 1, (c + STAGES - 1) % STAGES);
    }

    // -------- epilogue --------
    const int g = lane >> 2;
    const int ncol = (lane & 3) * 2;
#pragma unroll
    for (int mi = 0; mi < 4; mi++) {
        const int m0 = bm + warpM + mi*16 + g;
#pragma unroll
        for (int ni = 0; ni < 4; ni++) {
            const int n = bn + warpN + ni*8 + ncol;
            if (n >= N) continue;
            float v[4] = {acc[mi][ni][0], acc[mi][ni][1], acc[mi][ni][2], acc[mi][ni][3]};
            if (bias) {
                float b0 = bias[n], b1 = bias[n+1];
                v[0] += b0; v[1] += b1; v[2] += b0; v[3] += b1;
            }
            if (flags & 2) {
#pragma unroll
                for (int k = 0; k < 4; k++)
                    v[k] = (v[k] > 20.f) ? v[k] : log1pf(expf(v[k]));
            }
            float* p0 = C + (size_t)m0 * ldc + n;
            float* p1 = C + (size_t)(m0 + 8) * ldc + n;
            if (flags & 1) {
                float2 o0 = *(const float2*)p0, o1 = *(const float2*)p1;
                v[0] += o0.x; v[1] += o0.y; v[2] += o1.x; v[3] += o1.y;
            }
            *(float2*)p0 = make_float2(v[0], v[1]);
            *(float2*)p1 = make_float2(v[2], v[3]);
        }
    }
}

// ---------------- mask decoding (bool/int32/float32 robust) -----------------
__global__ void detect_mask_kernel(const unsigned char* __restrict__ mb) {
    __shared__ int s_weird, s_off, s_cnt[BSZ];
    int tid = threadIdx.x;
    if (tid == 0) { s_weird = 0; s_off = 0; }
    if (tid < BSZ) s_cnt[tid] = 0;
    __syncthreads();
    for (int i = tid; i < BSZ*TLEN; i += blockDim.x) {
        unsigned char c = mb[i];
        if (c > 1) s_weird = 1;
        else if (c && (i & 3)) s_off = 1;
    }
    __syncthreads();
    int mode = s_weird ? 2 : (s_off ? 0 : 1);
    for (int i = tid; i < BSZ*TLEN; i += blockDim.x) {
        int b = i / TLEN;
        int v;
        if (mode == 0)      v = mb[i];
        else if (mode == 1) v = ((const int*)mb)[i];
        else                v = (((const float*)mb)[i] != 0.0f);
        if (!v) atomicAdd(&s_cnt[b], 1);
    }
    __syncthreads();
    if (tid < BSZ) g_len[tid] = s_cnt[tid];
}

// ---------------- layernorm over DM=1024, one block per row -----------------
__global__ void layernorm_kernel(const float* __restrict__ x,
                                 const float* __restrict__ w,
                                 const float* __restrict__ bb,
                                 float* __restrict__ y)
{
    int row = blockIdx.x, tid = threadIdx.x;
    const float* xr = x + (size_t)row * DM_;
    float4 v = *(const float4*)(xr + tid * 4);
    float s  = v.x + v.y + v.z + v.w;
    float ss = v.x*v.x + v.y*v.y + v.z*v.z + v.w*v.w;
#pragma unroll
    for (int o = 16; o > 0; o >>= 1) {
        s  += __shfl_xor_sync(0xffffffffu, s, o);
        ss += __shfl_xor_sync(0xffffffffu, ss, o);
    }
    __shared__ float rs_[8], rss[8];
    int wid = tid >> 5, lane = tid & 31;
    if (lane == 0) { rs_[wid] = s; rss[wid] = ss; }
    __syncthreads();
    if (tid == 0) {
        float ts = 0.f, tss = 0.f;
        for (int i = 0; i < 8; i++) { ts += rs_[i]; tss += rss[i]; }
        rs_[0] = ts; rss[0] = tss;
    }
    __syncthreads();
    float mu  = rs_[0] * (1.f / DM_);
    float var = rss[0] * (1.f / DM_) - mu * mu;
    float inv = rsqrtf(var + 1e-5f);
    float4 wv = *(const float4*)(w + tid * 4);
    float4 bv = *(const float4*)(bb + tid * 4);
    float4 o;
    o.x = (v.x - mu) * inv * wv.x + bv.x;
    o.y = (v.y - mu) * inv * wv.y + bv.y;
    o.z = (v.z - mu) * inv * wv.z + bv.z;
    o.w = (v.w - mu) * inv * wv.w + bv.w;
    *(float4*)(y + (size_t)row * DM_ + tid * 4) = o;
}

// ---------------- causal depthwise conv (DC=4) + bias + silu ----------------
__global__ void conv_silu_kernel(const float* __restrict__ cw,
                                 const float* __restrict__ cb)
{
    size_t idx = (size_t)blockIdx.x * blockDim.x + threadIdx.x;
    int d = (int)(idx % DI_);
    size_t r = idx / DI_;
    int t = (int)(r % TLEN);
    const size_t base = r * (size_t)(2 * DI_) + d;
    float acc = cb[d];
#pragma unroll
    for (int j = 0; j < DC_; j++) {
        int tt = t - (DC_ - 1) + j;
        if (tt >= 0)
            acc += g_xz[base + (size_t)(j - (DC_ - 1)) * (2 * DI_)] * cw[d * DC_ + j];
    }
    float sg = 1.f / (1.f + __expf(-acc));
    g_u[r * DI_ + d] = acc * sg;
}

// ---------------- selective scan: one warp = 2 channels x 16 states ---------
__global__ void scan_kernel(const float* __restrict__ Alog,
                            const float* __restrict__ Dp)
{
    int gw   = (int)((blockIdx.x * blockDim.x + threadIdx.x) >> 5);
    int lane = threadIdx.x & 31;
    int b  = gw >> 10;
    int dp = gw & 1023;
    int s  = lane & 15;
    int half = lane >> 4;
    int d = dp * 2 + half;

    float Av = -expf(Alog[d * DS_ + s]);
    float Dv = Dp[d];
    float h = 0.f;

    for (int t = 0; t < TLEN; t++) {
        size_t row = (size_t)b * TLEN + t;
        float delta = g_delta[row * DI_ + d];
        float u     = g_u    [row * DI_ + d];
        float Bv = g_dbc[row * DBCW + DTR_ + s];
        float Cv = g_dbc[row * DBCW + DTR_ + DS_ + s];
        float e = __expf(delta * Av);
        h = h * e + (delta * u) * Bv;
        float p = h * Cv;
        p += __shfl_xor_sync(0xffffffffu, p, 1);
        p += __shfl_xor_sync(0xffffffffu, p, 2);
        p += __shfl_xor_sync(0xffffffffu, p, 4);
        p += __shfl_xor_sync(0xffffffffu, p, 8);
        if (s == 0) g_y[row * DI_ + d] = p + u * Dv;
    }
}

// ---------------- gate: y *= silu(z) ----------------------------------------
__global__ void gate_kernel()
{
    size_t idx = (size_t)blockIdx.x * blockDim.x + threadIdx.x;
    int d = (int)(idx % DI_);
    size_t r = idx / DI_;
    float z = g_xz[r * (size_t)(2 * DI_) + DI_ + d];
    float sg = z / (1.f + __expf(-z));
    g_y[idx] *= sg;
}

// ---------------- masked mean over time -------------------------------------
__global__ void mean_kernel(float* __restrict__ out)
{
    int b = blockIdx.y;
    int o = blockIdx.x * blockDim.x + threadIdx.x;
    int len = g_len[b];
    if (len < 1) len = 1;
    const float* p = g_ob + ((size_t)b * TLEN) * DO_ + o;
    float sum = 0.f;
    for (int t = 0; t < len; t++) sum += p[(size_t)t * DO_];
    out[b * DO_ + o] = sum / (float)len;
}

// ---------------- host-side GEMM wrapper ------------------------------------
static void run_gemm(const float* A, int lda, const float* W, int ldw,
                     const float* bias, float* C, int ldc,
                     int M, int N, int K, int flags,
                     __nv_bfloat16* abig, __nv_bfloat16* wbig)
{
    size_t na = (size_t)M * K, nw = (size_t)N * K;
    convert_split<<<(unsigned)((na + 255) / 256), 256>>>(A, lda, abig, M, K, 0);
    convert_split<<<(unsigned)((nw + 255) / 256), 256>>>(W, ldw, wbig, N, K, 1);
    int K3 = 3 * K;
    dim3 grid((N + 127) / 128, M / 128);
    gemm_mma<<<grid, 256, GTC_SMEM>>>(abig, K3, wbig, K3, bias, C, ldc, N, K3, flags);
}

// ---------------- launch ----------------------------------------------------
extern "C" void kernel_launch(void* const* d_in, const int* in_sizes, int n_in,
                              void* d_out, int out_size)
{
    const float* features  = (const float*)d_in[0];
    const void*  mask      = d_in[1];
    const float* inp_w     = (const float*)d_in[2];
    const float* inp_b     = (const float*)d_in[3];
    const float* norm_w    = (const float*)d_in[4];
    const float* norm_b    = (const float*)d_in[5];
    const float* in_proj_w = (const float*)d_in[6];
    const float* conv_w    = (const float*)d_in[7];
    const float* conv_b    = (const float*)d_in[8];
    const float* x_proj_w  = (const float*)d_in[9];
    const float* dt_proj_w = (const float*)d_in[10];
    const float* dt_proj_b = (const float*)d_in[11];
    const float* A_log     = (const float*)d_in[12];
    const float* Dskip     = (const float*)d_in[13];
    const float* mout_w    = (const float*)d_in[14];
    const float* out_w     = (const float*)d_in[15];
    const float* out_b     = (const float*)d_in[16];
    float* out = (float*)d_out;

    cudaFuncSetAttribute(gemm_mma, cudaFuncAttributeMaxDynamicSharedMemorySize, GTC_SMEM);

    float *px, *pxn, *pxz, *pu, *pdbc, *pdelta, *py, *pob;
    __nv_bfloat16 *pab, *pwb;
    cudaGetSymbolAddress((void**)&px,     g_x);
    cudaGetSymbolAddress((void**)&pxn,    g_xn);
    cudaGetSymbolAddress((void**)&pxz,    g_xz);
    cudaGetSymbolAddress((void**)&pu,     g_u);
    cudaGetSymbolAddress((void**)&pdbc,   g_dbc);
    cudaGetSymbolAddress((void**)&pdelta, g_delta);
    cudaGetSymbolAddress((void**)&py,     g_y);
    cudaGetSymbolAddress((void**)&pob,    g_ob);
    cudaGetSymbolAddress((void**)&pab,    g_abig);
    cudaGetSymbolAddress((void**)&pwb,    g_wbig);

    detect_mask_kernel<<<1, 256>>>((const unsigned char*)mask);

    // x = features @ inp_w^T + inp_b
    run_gemm(features, DIN_, inp_w, DIN_, inp_b, px, DM_, MROWS, DM_, DIN_, 0, pab, pwb);

    for (int l = 0; l < LNUM; l++) {
        layernorm_kernel<<<MROWS, 256>>>(px, norm_w + l*DM_, norm_b + l*DM_, pxn);

        // xz = xn @ in_proj_w^T
        run_gemm(pxn, DM_, in_proj_w + (size_t)l*2*DI_*DM_, DM_, nullptr,
                 pxz, 2*DI_, MROWS, 2*DI_, DM_, 0, pab, pwb);

        conv_silu_kernel<<<(unsigned)((MROWS*(size_t)DI_)/256), 256>>>(
            conv_w + (size_t)l*DI_*DC_, conv_b + l*DI_);

        // dbc = u @ x_proj_w^T
        run_gemm(pu, DI_, x_proj_w + (size_t)l*DBCW*DI_, DI_, nullptr,
                 pdbc, DBCW, MROWS, DBCW, DI_, 0, pab, pwb);

        // delta = softplus(dt @ dt_proj_w^T + dt_proj_b)
        run_gemm(pdbc, DBCW, dt_proj_w + (size_t)l*DI_*DTR_, DTR_,
                 dt_proj_b + l*DI_, pdelta, DI_, MROWS, DI_, DTR_, 2, pab, pwb);

        scan_kernel<<<512, 256>>>(A_log + (size_t)l*DI_*DS_, Dskip + l*DI_);

        gate_kernel<<<(unsigned)((MROWS*(size_t)DI_)/256), 256>>>();

        // x += (y*silu(z)) @ mout_w^T
        run_gemm(py, DI_, mout_w + (size_t)l*DM_*DI_, DI_, nullptr,
                 px, DM_, MROWS, DM_, DI_, 1, pab, pwb);
    }

    // ob = x @ out_w^T + out_b
    run_gemm(px, DM_, out_w, DM_, out_b, pob, DO_, MROWS, DO_, DM_, 0, pab, pwb);

    mean_kernel<<<dim3(DO_/256, BSZ), 256>>>(out);
}